// round 3
// baseline (speedup 1.0000x reference)
#include <cuda_runtime.h>
#include <math.h>

// Problem constants
#define BB    512     // batch
#define TT    64      // timesteps
#define EMBD  512     // embedding dim
#define HIDD  1024    // hidden dim
#define NG    4096    // 4*HIDD gates
#define NOUT  2048    // output features
#define KFULL (EMBD + HIDD)   // fused K for gates GEMM

// GEMM tiling
#define BM 128
#define BN 128
#define BK 16

// Persistent state (scratch) — __device__ globals per allocation rules
__device__ float g_h[BB * HIDD];
__device__ float g_c[BB * HIDD];
__device__ float g_gates[BB * NG];

__global__ void init_state_kernel() {
    int i = blockIdx.x * blockDim.x + threadIdx.x;
    g_h[i] = 0.0f;
    g_c[i] = 0.0f;
}

// MODE 0: gates = [emb[tok] | h] @ [W_ih | W_hh]^T + b_ih + b_hh   (M=512,N=4096,K=1536) -> g_gates
// MODE 1: out   = h @ W_out^T + b_out                              (M=512,N=2048,K=1024) -> out
template <int MODE>
__global__ __launch_bounds__(256, 2) void gemm_kernel(
    const int*   __restrict__ tok,
    const float* __restrict__ emb,
    const float* __restrict__ W1,     // W_ih (MODE0) / W_out (MODE1)
    const float* __restrict__ W2,     // W_hh (MODE0) / unused
    const float* __restrict__ bias1,  // b_ih / b_out
    const float* __restrict__ bias2,  // b_hh / unused
    float* __restrict__ out,          // unused in MODE0 (writes g_gates)
    int t)
{
    __shared__ __align__(16) float As[2][BK][BM];
    __shared__ __align__(16) float Bs[2][BK][BN];

    const int tid = threadIdx.x;
    const int bm  = blockIdx.y;
    const int bn  = blockIdx.x;

    // Loader mapping: each thread owns one A row + one B row, 8 contiguous k's
    const int lr = tid >> 1;          // 0..127
    const int lk = (tid & 1) * 8;     // 0 or 8

    const int arow = bm * BM + lr;
    const int ncol = bn * BN + lr;

    const float* aEmb;   // A source for k < EMBD (or whole A in MODE1)
    const float* aH;     // A source for k >= EMBD (offset so that +k0 works)
    const float* bLo;    // B source for k < EMBD (or whole B in MODE1)
    const float* bHi;

    if (MODE == 0) {
        aEmb = emb + (size_t)tok[arow * TT + t] * EMBD;
        aH   = g_h + (size_t)arow * HIDD - EMBD;
        bLo  = W1  + (size_t)ncol * EMBD;
        bHi  = W2  + (size_t)ncol * HIDD - EMBD;
    } else {
        aEmb = g_h + (size_t)arow * HIDD;
        aH   = nullptr;
        bLo  = W1  + (size_t)ncol * HIDD;
        bHi  = nullptr;
    }

    const int KT  = (MODE == 0) ? KFULL : HIDD;
    const int NKT = KT / BK;

    const int ty = tid >> 4;   // 0..15
    const int tx = tid & 15;   // 0..15

    float acc[8][8];
#pragma unroll
    for (int i = 0; i < 8; i++)
#pragma unroll
        for (int j = 0; j < 8; j++) acc[i][j] = 0.0f;

    float4 pa0, pa1, pb0, pb1;

    auto load_tile = [&](int kt) {
        const int k0 = kt * BK;
        const float* ap;
        const float* bp;
        if (MODE == 0) {
            ap = ((k0 < EMBD) ? aEmb : aH) + k0 + lk;
            bp = ((k0 < EMBD) ? bLo  : bHi) + k0 + lk;
        } else {
            ap = aEmb + k0 + lk;
            bp = bLo  + k0 + lk;
        }
        pa0 = *(const float4*)(ap);
        pa1 = *(const float4*)(ap + 4);
        pb0 = *(const float4*)(bp);
        pb1 = *(const float4*)(bp + 4);
    };

    auto store_tile = [&](int buf) {
        As[buf][lk + 0][lr] = pa0.x; As[buf][lk + 1][lr] = pa0.y;
        As[buf][lk + 2][lr] = pa0.z; As[buf][lk + 3][lr] = pa0.w;
        As[buf][lk + 4][lr] = pa1.x; As[buf][lk + 5][lr] = pa1.y;
        As[buf][lk + 6][lr] = pa1.z; As[buf][lk + 7][lr] = pa1.w;
        Bs[buf][lk + 0][lr] = pb0.x; Bs[buf][lk + 1][lr] = pb0.y;
        Bs[buf][lk + 2][lr] = pb0.z; Bs[buf][lk + 3][lr] = pb0.w;
        Bs[buf][lk + 4][lr] = pb1.x; Bs[buf][lk + 5][lr] = pb1.y;
        Bs[buf][lk + 6][lr] = pb1.z; Bs[buf][lk + 7][lr] = pb1.w;
    };

    load_tile(0);
    store_tile(0);
    __syncthreads();

    for (int kt = 0; kt < NKT; kt++) {
        const int cur = kt & 1;
        if (kt + 1 < NKT) load_tile(kt + 1);

#pragma unroll
        for (int kk = 0; kk < BK; kk++) {
            float4 a0 = *(const float4*)&As[cur][kk][ty * 8];
            float4 a1 = *(const float4*)&As[cur][kk][ty * 8 + 4];
            float4 b0 = *(const float4*)&Bs[cur][kk][tx * 8];
            float4 b1 = *(const float4*)&Bs[cur][kk][tx * 8 + 4];
            float av[8] = {a0.x, a0.y, a0.z, a0.w, a1.x, a1.y, a1.z, a1.w};
            float bv[8] = {b0.x, b0.y, b0.z, b0.w, b1.x, b1.y, b1.z, b1.w};
#pragma unroll
            for (int i = 0; i < 8; i++)
#pragma unroll
                for (int j = 0; j < 8; j++)
                    acc[i][j] = fmaf(av[i], bv[j], acc[i][j]);
        }

        if (kt + 1 < NKT) store_tile(cur ^ 1);
        __syncthreads();
    }

    // Epilogue
    const int row0 = bm * BM + ty * 8;
    const int col0 = bn * BN + tx * 8;
    float bias[8];
#pragma unroll
    for (int j = 0; j < 8; j++) {
        bias[j] = bias1[col0 + j] + ((MODE == 0) ? bias2[col0 + j] : 0.0f);
    }
    float* outp = (MODE == 0) ? g_gates : out;
    const int ldo = (MODE == 0) ? NG : NOUT;
#pragma unroll
    for (int i = 0; i < 8; i++) {
        float4 v0 = make_float4(acc[i][0] + bias[0], acc[i][1] + bias[1],
                                acc[i][2] + bias[2], acc[i][3] + bias[3]);
        float4 v1 = make_float4(acc[i][4] + bias[4], acc[i][5] + bias[5],
                                acc[i][6] + bias[6], acc[i][7] + bias[7]);
        *(float4*)&outp[(size_t)(row0 + i) * ldo + col0]     = v0;
        *(float4*)&outp[(size_t)(row0 + i) * ldo + col0 + 4] = v1;
    }
}

__device__ __forceinline__ float sigmoidf_(float x) {
    return 1.0f / (1.0f + expf(-x));
}

__global__ void lstm_update_kernel() {
    int idx = blockIdx.x * blockDim.x + threadIdx.x;  // < BB*HIDD
    int b = idx >> 10;        // /HIDD
    int j = idx & (HIDD - 1);
    const float* gb = g_gates + (size_t)b * NG;
    float xi = gb[j];
    float xf = gb[j + HIDD];
    float xg = gb[j + 2 * HIDD];
    float xo = gb[j + 3 * HIDD];
    float i_ = sigmoidf_(xi);
    float f_ = sigmoidf_(xf);
    float g_ = tanhf(xg);
    float o_ = sigmoidf_(xo);
    float c_ = f_ * g_c[idx] + i_ * g_;
    g_c[idx] = c_;
    g_h[idx] = o_ * tanhf(c_);
}

extern "C" void kernel_launch(void* const* d_in, const int* in_sizes, int n_in,
                              void* d_out, int out_size) {
    const int*   m     = (const int*)  d_in[0];
    const float* emb   = (const float*)d_in[1];
    const float* W_ih  = (const float*)d_in[2];
    const float* W_hh  = (const float*)d_in[3];
    const float* b_ih  = (const float*)d_in[4];
    const float* b_hh  = (const float*)d_in[5];
    const float* W_out = (const float*)d_in[6];
    const float* b_out = (const float*)d_in[7];
    float* out = (float*)d_out;

    dim3 blk(256);
    dim3 grid_init((BB * HIDD) / 256);
    dim3 grid_g(NG / BN, BB / BM);     // (32, 4)
    dim3 grid_o(NOUT / BN, BB / BM);   // (16, 4)

    init_state_kernel<<<grid_init, blk>>>();

    for (int t = 0; t < TT; t++) {
        gemm_kernel<0><<<grid_g, blk>>>(m, emb, W_ih, W_hh, b_ih, b_hh, nullptr, t);
        lstm_update_kernel<<<grid_init, blk>>>();
    }

    gemm_kernel<1><<<grid_o, blk>>>(nullptr, nullptr, W_out, nullptr, b_out, nullptr, out, 0);
}

// round 7
// speedup vs baseline: 2.5622x; 2.5622x over previous
#include <cuda_runtime.h>
#include <cuda_bf16.h>
#include <math.h>
#include <stdint.h>

// ---------------- problem constants ----------------
#define BB    512
#define TT    64
#define EMBD  512
#define HIDD  1024
#define NG    4096
#define NOUT  2048
#define KIN   (EMBD + HIDD)     // 1536
#define KG    (3 * KIN)         // 4608  (split-precision expanded K, gates)
#define KO    (3 * HIDD)        // 3072  (expanded K, output proj)
#define NCHUNK_G (KG / 64)      // 72
#define NCHUNK_O (KO / 64)      // 48
#define SMEM_DYN (2 * 32768 + 256)

// ---------------- persistent device scratch ----------------
__device__ float g_h[BB * HIDD];
__device__ float g_c[BB * HIDD];
__device__ float g_gates[BB * NG];
__device__ __align__(16) __nv_bfloat16 g_A [BB * KG];
__device__ __align__(16) __nv_bfloat16 g_Ao[BB * KO];
__device__ __align__(16) __nv_bfloat16 g_Wg[(size_t)NG * KG];
__device__ __align__(16) __nv_bfloat16 g_Wo[(size_t)NOUT * KO];

// ---------------- helpers ----------------
__device__ __forceinline__ uint32_t smem_u32(const void* p) {
    uint32_t a;
    asm("{ .reg .u64 t; cvta.to.shared.u64 t, %1; cvt.u32.u64 %0, t; }" : "=r"(a) : "l"(p));
    return a;
}

__device__ __forceinline__ void split_bf16(float v, __nv_bfloat16& hi, __nv_bfloat16& lo) {
    hi = __float2bfloat16(v);
    lo = __float2bfloat16(v - __bfloat162float(hi));
}

__device__ __forceinline__ void cp_async16(uint32_t dst, const void* src) {
    asm volatile("cp.async.cg.shared.global [%0], [%1], 16;" :: "r"(dst), "l"(src));
}
__device__ __forceinline__ void cp_commit() {
    asm volatile("cp.async.commit_group;" ::: "memory");
}

__device__ __forceinline__ void ldsm_x4(uint32_t* r, uint32_t addr) {
    asm volatile("ldmatrix.sync.aligned.m8n8.x4.shared.b16 {%0,%1,%2,%3}, [%4];"
                 : "=r"(r[0]), "=r"(r[1]), "=r"(r[2]), "=r"(r[3]) : "r"(addr));
}

__device__ __forceinline__ void mma16816(float* d, const uint32_t* a, uint32_t b0, uint32_t b1) {
    asm volatile(
        "mma.sync.aligned.m16n8k16.row.col.f32.bf16.bf16.f32 "
        "{%0,%1,%2,%3}, {%4,%5,%6,%7}, {%8,%9}, {%0,%1,%2,%3};"
        : "+f"(d[0]), "+f"(d[1]), "+f"(d[2]), "+f"(d[3])
        : "r"(a[0]), "r"(a[1]), "r"(a[2]), "r"(a[3]), "r"(b0), "r"(b1));
}

// ---------------- setup kernels ----------------
__global__ void init_state_kernel() {
    int i = blockIdx.x * blockDim.x + threadIdx.x;
    g_h[i] = 0.0f;
    g_c[i] = 0.0f;
}

// B' rows: [Bh | Bh | Bl]
__global__ void conv_wg_kernel(const float* __restrict__ W_ih, const float* __restrict__ W_hh) {
    int idx = blockIdx.x * 256 + threadIdx.x;   // NG*KIN
    int n = idx / KIN, k = idx - n * KIN;
    float w = (k < EMBD) ? W_ih[n * EMBD + k] : W_hh[n * HIDD + (k - EMBD)];
    __nv_bfloat16 hi, lo; split_bf16(w, hi, lo);
    size_t r = (size_t)n * KG;
    g_Wg[r + k] = hi;
    g_Wg[r + KIN + k] = hi;
    g_Wg[r + 2 * KIN + k] = lo;
}

__global__ void conv_wo_kernel(const float* __restrict__ W_out) {
    int idx = blockIdx.x * 256 + threadIdx.x;   // NOUT*HIDD
    int n = idx / HIDD, k = idx - n * HIDD;
    __nv_bfloat16 hi, lo; split_bf16(W_out[n * HIDD + k], hi, lo);
    size_t r = (size_t)n * KO;
    g_Wo[r + k] = hi;
    g_Wo[r + HIDD + k] = hi;
    g_Wo[r + 2 * HIDD + k] = lo;
}

// A' rows: [Ah | Al | Ah]
__global__ void build_A_kernel(const int* __restrict__ tok, const float* __restrict__ emb, int t) {
    int idx = blockIdx.x * 256 + threadIdx.x;   // BB*KIN
    int b = idx / KIN, k = idx - b * KIN;
    float v = (k < EMBD) ? emb[(size_t)tok[b * TT + t] * EMBD + k]
                         : g_h[b * HIDD + (k - EMBD)];
    __nv_bfloat16 hi, lo; split_bf16(v, hi, lo);
    size_t r = (size_t)b * KG;
    g_A[r + k] = hi;
    g_A[r + KIN + k] = lo;
    g_A[r + 2 * KIN + k] = hi;
}

__global__ void build_Ao_kernel() {
    int idx = blockIdx.x * 256 + threadIdx.x;   // BB*HIDD
    int b = idx / HIDD, k = idx - b * HIDD;
    __nv_bfloat16 hi, lo; split_bf16(g_h[b * HIDD + k], hi, lo);
    size_t r = (size_t)b * KO;
    g_Ao[r + k] = hi;
    g_Ao[r + HIDD + k] = lo;
    g_Ao[r + 2 * HIDD + k] = hi;
}

// ---------------- mma.sync GEMM: C[M, Ntot] = A[M, K'] * B[Ntot, K']^T ----------------
// CTA 128x128, 8 warps (2x4), warp tile 64x32, K-slab 64 (128B rows, SW128 swizzle),
// 2-stage cp.async double buffer. bf16 HMMA with f32 accumulation.
template <int MODE>   // 0 = gates (C=g_gates), 1 = output (C=Cout, +bias)
__global__ __launch_bounds__(256, 1) void mma_gemm(float* __restrict__ Cout,
                                                   const float* __restrict__ bias) {
    constexpr int NCHUNK = (MODE == 0) ? NCHUNK_G : NCHUNK_O;
    constexpr int KLD    = NCHUNK * 64;
    constexpr int LDC    = (MODE == 0) ? NG : NOUT;
    const __nv_bfloat16* A  = (MODE == 0) ? g_A  : g_Ao;
    const __nv_bfloat16* Bw = (MODE == 0) ? g_Wg : g_Wo;
    float* C = (MODE == 0) ? g_gates : Cout;

    extern __shared__ char dyn[];
    const uint32_t sbase = (smem_u32(dyn) + 127u) & ~127u;
    // stage s: A tile at sbase + s*32768 (16KB), B tile at +16384

    const int tid  = threadIdx.x;
    const int wid  = tid >> 5, lane = tid & 31;
    const int m0 = blockIdx.y * 128, n0 = blockIdx.x * 128;
    const int w_m = (wid >> 2) * 64;   // 0 / 64
    const int w_n = (wid & 3) * 32;    // 0..96

    // ----- cp.async loader: 256 threads, 16B each, 4 iters per tile -----
    const int lr = tid >> 3;          // 0..31
    const int lsB = (tid & 7) * 16;   // byte seg within 128B row
    auto issue = [&](int kc) {
        const uint32_t st = sbase + (kc & 1) * 32768;
        const __nv_bfloat16* ag = A  + (size_t)(m0 + lr) * KLD + kc * 64 + (lsB >> 1);
        const __nv_bfloat16* bg = Bw + (size_t)(n0 + lr) * KLD + kc * 64 + (lsB >> 1);
#pragma unroll
        for (int i = 0; i < 4; i++) {
            uint32_t off = (uint32_t)(lr + i * 32) * 128u + (uint32_t)lsB;
            uint32_t sw  = off ^ ((off >> 3) & 0x70u);
            cp_async16(st + sw, ag + (size_t)i * 32 * KLD);
            cp_async16(st + 16384 + sw, bg + (size_t)i * 32 * KLD);
        }
        cp_commit();
    };

    // ----- per-lane ldmatrix base offsets (pre-swizzle) -----
    const int q  = lane >> 3;      // 0..3
    const int r8 = lane & 7;
    // A x4 quadrants: q0:(r+0,k+0) q1:(r+8,k+0) q2:(r+0,k+8) q3:(r+8,k+8)
    const uint32_t arow = (uint32_t)(w_m + (q & 1) * 8 + r8);
    const uint32_t akb  = (uint32_t)((q >> 1) * 16);
    // B x4 quadrants: q0:(n+0,k+0) q1:(n+0,k+8) q2:(n+8,k+0) q3:(n+8,k+8)
    const uint32_t brow = (uint32_t)(w_n + (q >> 1) * 8 + r8);
    const uint32_t bkb  = (uint32_t)((q & 1) * 16);

    float acc[4][4][4];
#pragma unroll
    for (int i = 0; i < 4; i++)
#pragma unroll
        for (int j = 0; j < 4; j++)
#pragma unroll
            for (int v = 0; v < 4; v++) acc[i][j][v] = 0.0f;

    issue(0);

    for (int kc = 0; kc < NCHUNK; kc++) {
        if (kc + 1 < NCHUNK) {
            issue(kc + 1);
            asm volatile("cp.async.wait_group 1;" ::: "memory");
        } else {
            asm volatile("cp.async.wait_group 0;" ::: "memory");
        }
        __syncthreads();

        const uint32_t stA = sbase + (kc & 1) * 32768;
        const uint32_t stB = stA + 16384;

#pragma unroll
        for (int kk = 0; kk < 4; kk++) {
            uint32_t afr[4][4];
#pragma unroll
            for (int mi = 0; mi < 4; mi++) {
                uint32_t off = (arow + mi * 16) * 128u + kk * 32u + akb;
                ldsm_x4(afr[mi], stA + (off ^ ((off >> 3) & 0x70u)));
            }
            uint32_t bfr[2][4];
#pragma unroll
            for (int nj2 = 0; nj2 < 2; nj2++) {
                uint32_t off = (brow + nj2 * 16) * 128u + kk * 32u + bkb;
                ldsm_x4(bfr[nj2], stB + (off ^ ((off >> 3) & 0x70u)));
            }
#pragma unroll
            for (int mi = 0; mi < 4; mi++)
#pragma unroll
                for (int nj = 0; nj < 4; nj++)
                    mma16816(acc[mi][nj], afr[mi],
                             bfr[nj >> 1][(nj & 1) * 2], bfr[nj >> 1][(nj & 1) * 2 + 1]);
        }
        __syncthreads();
    }

    // ----- epilogue -----
    const int lrow = lane >> 2;        // 0..7
    const int lcol = (lane & 3) * 2;   // 0,2,4,6
#pragma unroll
    for (int mi = 0; mi < 4; mi++) {
#pragma unroll
        for (int nj = 0; nj < 4; nj++) {
            int row0 = m0 + w_m + mi * 16 + lrow;
            int col  = n0 + w_n + nj * 8 + lcol;
            float b0 = 0.0f, b1 = 0.0f;
            if (MODE == 1) { b0 = __ldg(&bias[col]); b1 = __ldg(&bias[col + 1]); }
            *(float2*)&C[(size_t)row0 * LDC + col] =
                make_float2(acc[mi][nj][0] + b0, acc[mi][nj][1] + b1);
            *(float2*)&C[(size_t)(row0 + 8) * LDC + col] =
                make_float2(acc[mi][nj][2] + b0, acc[mi][nj][3] + b1);
        }
    }
}

// ---------------- LSTM pointwise (adds biases here) ----------------
__device__ __forceinline__ float sigmoidf_(float x) { return 1.0f / (1.0f + expf(-x)); }

__global__ void lstm_update_kernel(const float* __restrict__ b_ih, const float* __restrict__ b_hh) {
    int idx = blockIdx.x * blockDim.x + threadIdx.x;  // < BB*HIDD
    int b = idx >> 10;
    int j = idx & (HIDD - 1);
    const float* gb = g_gates + (size_t)b * NG;
    float xi = gb[j]            + b_ih[j]            + b_hh[j];
    float xf = gb[j +     HIDD] + b_ih[j +     HIDD] + b_hh[j +     HIDD];
    float xg = gb[j + 2 * HIDD] + b_ih[j + 2 * HIDD] + b_hh[j + 2 * HIDD];
    float xo = gb[j + 3 * HIDD] + b_ih[j + 3 * HIDD] + b_hh[j + 3 * HIDD];
    float i_ = sigmoidf_(xi);
    float f_ = sigmoidf_(xf);
    float g_ = tanhf(xg);
    float o_ = sigmoidf_(xo);
    float c_ = f_ * g_c[idx] + i_ * g_;
    g_c[idx] = c_;
    g_h[idx] = o_ * tanhf(c_);
}

// ---------------- launch ----------------
extern "C" void kernel_launch(void* const* d_in, const int* in_sizes, int n_in,
                              void* d_out, int out_size) {
    const int*   m     = (const int*)  d_in[0];
    const float* emb   = (const float*)d_in[1];
    const float* W_ih  = (const float*)d_in[2];
    const float* W_hh  = (const float*)d_in[3];
    const float* b_ih  = (const float*)d_in[4];
    const float* b_hh  = (const float*)d_in[5];
    const float* W_out = (const float*)d_in[6];
    const float* b_out = (const float*)d_in[7];
    float* out = (float*)d_out;

    cudaFuncSetAttribute(mma_gemm<0>, cudaFuncAttributeMaxDynamicSharedMemorySize, SMEM_DYN);
    cudaFuncSetAttribute(mma_gemm<1>, cudaFuncAttributeMaxDynamicSharedMemorySize, SMEM_DYN);

    init_state_kernel<<<(BB * HIDD) / 256, 256>>>();
    conv_wg_kernel<<<(NG * KIN) / 256, 256>>>(W_ih, W_hh);
    conv_wo_kernel<<<(NOUT * HIDD) / 256, 256>>>(W_out);

    for (int t = 0; t < TT; t++) {
        build_A_kernel<<<(BB * KIN) / 256, 256>>>(m, emb, t);
        mma_gemm<0><<<dim3(NG / 128, BB / 128), 256, SMEM_DYN>>>(nullptr, nullptr);
        lstm_update_kernel<<<(BB * HIDD) / 256, 256>>>(b_ih, b_hh);
    }

    build_Ao_kernel<<<(BB * HIDD) / 256, 256>>>();
    mma_gemm<1><<<dim3(NOUT / 128, BB / 128), 256, SMEM_DYN>>>(out, b_out);
}